// round 1
// baseline (speedup 1.0000x reference)
#include <cuda_runtime.h>
#include <cuda_bf16.h>
#include <cstdint>

#define BB 2
#define QQ 300
#define TT 300
#define HH 256
#define WW 256
#define PP 12544
#define SPLITK 7
#define KC (PP / SPLITK)     // 1792
#define KITERS (KC / 64)     // 28
#define NTILES 5             // ceil(300/64)

// ---------------- scratch (device globals; no allocation allowed) ----------------
__device__ __nv_bfloat16 g_om[(size_t)BB * QQ * PP];
__device__ __nv_bfloat16 g_s [(size_t)BB * QQ * PP];
__device__ __nv_bfloat16 g_tm[(size_t)BB * TT * PP];
__device__ float g_negsum[BB * QQ];
__device__ float g_ssum [BB * QQ];
__device__ float g_tmsum [BB * TT];
__device__ float g_D1p[(size_t)SPLITK * BB * QQ * TT];
__device__ float g_D2p[(size_t)SPLITK * BB * QQ * TT];

// ---------------- kernel 1: bilinear point sampling + row sums ----------------
__global__ __launch_bounds__(256) void sample_kernel(
    const float* __restrict__ pred_masks,
    const float* __restrict__ tgt_masks,
    const float* __restrict__ point_coords)
{
    int bx = blockIdx.x;
    int b = bx / (QQ + TT);
    int r = bx % (QQ + TT);
    bool is_pred = (r < QQ);
    int m = is_pred ? r : r - QQ;

    const float* mask = (is_pred ? pred_masks : tgt_masks) + ((size_t)(b * 300 + m)) * (HH * WW);
    const float2* pc = (const float2*)(point_coords + (size_t)b * PP * 2);
    size_t obase = (size_t)(b * 300 + m) * PP;

    float s0 = 0.f, s1 = 0.f;
    for (int p = threadIdx.x; p < PP; p += 256) {
        float2 pt = pc[p];
        float x = pt.x * (float)WW - 0.5f;
        float y = pt.y * (float)HH - 0.5f;
        float x0f = floorf(x), y0f = floorf(y);
        float wx = x - x0f, wy = y - y0f;
        int x0 = (int)x0f, y0 = (int)y0f;
        int x1 = x0 + 1, y1 = y0 + 1;

        bool vx0 = (x0 >= 0) & (x0 < WW);
        bool vx1 = (x1 >= 0) & (x1 < WW);
        bool vy0 = (y0 >= 0) & (y0 < HH);
        bool vy1 = (y1 >= 0) & (y1 < HH);
        int xc0 = min(max(x0, 0), WW - 1);
        int xc1 = min(max(x1, 0), WW - 1);
        int yc0 = min(max(y0, 0), HH - 1);
        int yc1 = min(max(y1, 0), HH - 1);

        float f00 = (vx0 && vy0) ? __ldg(mask + yc0 * WW + xc0) : 0.f;
        float f01 = (vx1 && vy0) ? __ldg(mask + yc0 * WW + xc1) : 0.f;
        float f10 = (vx0 && vy1) ? __ldg(mask + yc1 * WW + xc0) : 0.f;
        float f11 = (vx1 && vy1) ? __ldg(mask + yc1 * WW + xc1) : 0.f;

        float om = f00 * (1.f - wy) * (1.f - wx) + f01 * (1.f - wy) * wx +
                   f10 * wy * (1.f - wx) + f11 * wy * wx;

        if (is_pred) {
            float sg = 1.f / (1.f + __expf(-om));
            float neg = fmaxf(om, 0.f) + log1pf(__expf(-fabsf(om)));  // softplus(om)
            g_om[obase + p] = __float2bfloat16(om);
            g_s [obase + p] = __float2bfloat16(sg);
            s0 += neg;
            s1 += sg;
        } else {
            g_tm[obase + p] = __float2bfloat16(om);
            s0 += om;
        }
    }

    // block reduction (8 warps)
    #pragma unroll
    for (int o = 16; o > 0; o >>= 1) {
        s0 += __shfl_down_sync(0xffffffffu, s0, o);
        s1 += __shfl_down_sync(0xffffffffu, s1, o);
    }
    __shared__ float r0[8], r1[8];
    int lane = threadIdx.x & 31, warp = threadIdx.x >> 5;
    if (lane == 0) { r0[warp] = s0; r1[warp] = s1; }
    __syncthreads();
    if (threadIdx.x == 0) {
        float t0 = 0.f, t1 = 0.f;
        #pragma unroll
        for (int i = 0; i < 8; i++) { t0 += r0[i]; t1 += r1[i]; }
        if (is_pred) {
            g_negsum[b * 300 + m] = t0;
            g_ssum [b * 300 + m] = t1;
        } else {
            g_tmsum[b * 300 + m] = t0;
        }
    }
}

// ---------------- mma helpers ----------------
__device__ __forceinline__ void ldsm_x4(uint32_t* r, const void* ptr) {
    uint32_t a = (uint32_t)__cvta_generic_to_shared(ptr);
    asm volatile("ldmatrix.sync.aligned.m8n8.x4.shared.b16 {%0,%1,%2,%3}, [%4];"
                 : "=r"(r[0]), "=r"(r[1]), "=r"(r[2]), "=r"(r[3]) : "r"(a));
}
__device__ __forceinline__ void ldsm_x2(uint32_t* r, const void* ptr) {
    uint32_t a = (uint32_t)__cvta_generic_to_shared(ptr);
    asm volatile("ldmatrix.sync.aligned.m8n8.x2.shared.b16 {%0,%1}, [%2];"
                 : "=r"(r[0]), "=r"(r[1]) : "r"(a));
}
__device__ __forceinline__ void mma16816(float* d, const uint32_t* a, const uint32_t* b) {
    asm volatile("mma.sync.aligned.m16n8k16.row.col.f32.bf16.bf16.f32 "
                 "{%0,%1,%2,%3}, {%4,%5,%6,%7}, {%8,%9}, {%0,%1,%2,%3};"
                 : "+f"(d[0]), "+f"(d[1]), "+f"(d[2]), "+f"(d[3])
                 : "r"(a[0]), "r"(a[1]), "r"(a[2]), "r"(a[3]), "r"(b[0]), "r"(b[1]));
}

// ---------------- kernel 2: dual bf16 GEMM (om*tm^T and s*tm^T), split-K ----------------
#define LDT 72  // 64 + 8 pad (bf16 elems), row pitch 144B -> conflict-free ldmatrix

__global__ __launch_bounds__(256) void gemm_kernel()
{
    int bx = blockIdx.x;
    int split = bx % SPLITK; bx /= SPLITK;
    int tt = bx % NTILES; bx /= NTILES;
    int qt = bx % NTILES;
    int b  = bx / NTILES;
    int m0 = qt * 64, n0 = tt * 64;

    __shared__ __nv_bfloat16 s_om[64 * LDT];
    __shared__ __nv_bfloat16 s_s [64 * LDT];
    __shared__ __nv_bfloat16 s_tm[64 * LDT];

    int tid = threadIdx.x;
    int warp = tid >> 5, lane = tid & 31;
    int wm0 = (warp >> 2) * 32;   // 2 warps along m
    int wn0 = (warp & 3) * 16;    // 4 warps along n

    float acc1[2][2][4];
    float acc2[2][2][4];
    #pragma unroll
    for (int i = 0; i < 2; i++)
        #pragma unroll
        for (int j = 0; j < 2; j++)
            #pragma unroll
            for (int k = 0; k < 4; k++) { acc1[i][j][k] = 0.f; acc2[i][j][k] = 0.f; }

    const __nv_bfloat16* Aom = g_om + (size_t)(b * 300) * PP;
    const __nv_bfloat16* As  = g_s  + (size_t)(b * 300) * PP;
    const __nv_bfloat16* Btm = g_tm + (size_t)(b * 300) * PP;

    int kbase = split * KC;
    for (int kt = 0; kt < KITERS; ++kt) {
        int k0 = kbase + kt * 64;
        // cooperative load of 3 tiles (64 rows x 64 bf16 = 128B/row)
        #pragma unroll
        for (int i = tid; i < 512; i += 256) {
            int row = i >> 3;
            int c = (i & 7) * 8;  // bf16 col offset, 16B chunks
            int gq = m0 + row;
            int gt = n0 + row;
            uint4 z = make_uint4(0, 0, 0, 0);
            uint4 vo = z, vs = z, vt = z;
            if (gq < 300) {
                vo = __ldg((const uint4*)(Aom + (size_t)gq * PP + k0 + c));
                vs = __ldg((const uint4*)(As  + (size_t)gq * PP + k0 + c));
            }
            if (gt < 300) {
                vt = __ldg((const uint4*)(Btm + (size_t)gt * PP + k0 + c));
            }
            *(uint4*)&s_om[row * LDT + c] = vo;
            *(uint4*)&s_s [row * LDT + c] = vs;
            *(uint4*)&s_tm[row * LDT + c] = vt;
        }
        __syncthreads();

        #pragma unroll
        for (int ks = 0; ks < 4; ++ks) {
            uint32_t ao[2][4], av[2][4], bb[2][2];
            int arow = wm0 + (lane & 15);
            int acol = ks * 16 + (lane >> 4) * 8;
            #pragma unroll
            for (int ti = 0; ti < 2; ++ti) {
                ldsm_x4(ao[ti], &s_om[(arow + ti * 16) * LDT + acol]);
                ldsm_x4(av[ti], &s_s [(arow + ti * 16) * LDT + acol]);
            }
            int l16 = lane & 15;
            int brow = wn0 + (l16 & 7);
            int bcol = ks * 16 + (l16 >> 3) * 8;
            #pragma unroll
            for (int tn = 0; tn < 2; ++tn) {
                ldsm_x2(bb[tn], &s_tm[(brow + tn * 8) * LDT + bcol]);
            }
            #pragma unroll
            for (int ti = 0; ti < 2; ++ti)
                #pragma unroll
                for (int tn = 0; tn < 2; ++tn) {
                    mma16816(acc1[ti][tn], ao[ti], bb[tn]);
                    mma16816(acc2[ti][tn], av[ti], bb[tn]);
                }
        }
        __syncthreads();
    }

    // write split-K partials (deterministic, one owner per slot)
    float* D1 = g_D1p + ((size_t)(split * BB + b)) * (QQ * TT);
    float* D2 = g_D2p + ((size_t)(split * BB + b)) * (QQ * TT);
    #pragma unroll
    for (int ti = 0; ti < 2; ++ti)
        #pragma unroll
        for (int tn = 0; tn < 2; ++tn)
            #pragma unroll
            for (int rh = 0; rh < 2; ++rh) {  // rh selects rows m and m+8 (regs {0,1} vs {2,3})
                int q = m0 + wm0 + ti * 16 + (lane >> 2) + rh * 8;
                int t = n0 + wn0 + tn * 8 + (lane & 3) * 2;
                if (q < QQ && t < TT) {
                    float2 v1 = make_float2(acc1[ti][tn][rh * 2 + 0], acc1[ti][tn][rh * 2 + 1]);
                    float2 v2 = make_float2(acc2[ti][tn][rh * 2 + 0], acc2[ti][tn][rh * 2 + 1]);
                    *(float2*)&D1[q * TT + t] = v1;
                    *(float2*)&D2[q * TT + t] = v2;
                }
            }
}

// ---------------- kernel 3: reduce partials + box costs + assemble ----------------
__global__ __launch_bounds__(256) void final_kernel(
    const float* __restrict__ pred_boxes,
    const float* __restrict__ tgt_boxes,
    float* __restrict__ out)
{
    int idx = blockIdx.x * 256 + threadIdx.x;
    if (idx >= BB * QQ * TT) return;
    int b = idx / (QQ * TT);
    int r = idx % (QQ * TT);
    int q = r / TT, t = r % TT;

    float D1 = 0.f, D2 = 0.f;
    #pragma unroll
    for (int s = 0; s < SPLITK; ++s) {
        size_t off = ((size_t)(s * BB + b)) * (QQ * TT) + r;
        D1 += g_D1p[off];
        D2 += g_D2p[off];
    }

    float ns = g_negsum[b * 300 + q];
    float ss = g_ssum [b * 300 + q];
    float ts = g_tmsum [b * 300 + t];

    float cost_mask = (ns - D1) * (1.f / (float)PP);
    float cost_dice = 1.f - (2.f * D2 + 1.f) / (ss + ts + 1.f);

    const float* pb = pred_boxes + (size_t)(b * 300 + q) * 4;
    const float* tb = tgt_boxes  + (size_t)(b * 300 + t) * 4;
    float p0 = pb[0], p1 = pb[1], p2 = pb[2], p3 = pb[3];
    float t0 = tb[0], t1 = tb[1], t2 = tb[2], t3 = tb[3];

    float cost_bbox = fabsf(p0 - t0) + fabsf(p1 - t1) + fabsf(p2 - t2) + fabsf(p3 - t3);

    // cxcywh -> xyxy
    float ax0 = p0 - 0.5f * p2, ay0 = p1 - 0.5f * p3;
    float ax1 = p0 + 0.5f * p2, ay1 = p1 + 0.5f * p3;
    float bx0 = t0 - 0.5f * t2, by0 = t1 - 0.5f * t3;
    float bx1 = t0 + 0.5f * t2, by1 = t1 + 0.5f * t3;

    float areaA = (ax1 - ax0) * (ay1 - ay0);
    float areaB = (bx1 - bx0) * (by1 - by0);
    float iw = fminf(ax1, bx1) - fmaxf(ax0, bx0);
    float ih = fminf(ay1, by1) - fmaxf(ay0, by0);
    iw = fmaxf(iw, 0.f); ih = fmaxf(ih, 0.f);
    float inter = iw * ih;
    float uni = areaA + areaB - inter;
    float iou = inter / uni;
    float ew = fmaxf(ax1, bx1) - fminf(ax0, bx0);
    float eh = fmaxf(ay1, by1) - fminf(ay0, by0);
    ew = fmaxf(ew, 0.f); eh = fmaxf(eh, 0.f);
    float ae = ew * eh;
    float giou = iou - (ae - uni) / ae;

    out[idx] = 5.f * cost_mask + 5.f * cost_dice + 5.f * cost_bbox - 2.f * giou;
}

// ---------------- launch ----------------
extern "C" void kernel_launch(void* const* d_in, const int* in_sizes, int n_in,
                              void* d_out, int out_size)
{
    const float* pred_masks   = (const float*)d_in[0];
    const float* tgt_masks    = (const float*)d_in[1];
    const float* pred_boxes   = (const float*)d_in[2];
    const float* tgt_boxes    = (const float*)d_in[3];
    const float* point_coords = (const float*)d_in[4];
    float* out = (float*)d_out;

    sample_kernel<<<BB * (QQ + TT), 256>>>(pred_masks, tgt_masks, point_coords);
    gemm_kernel<<<BB * NTILES * NTILES * SPLITK, 256>>>();
    final_kernel<<<(BB * QQ * TT + 255) / 256, 256>>>(pred_boxes, tgt_boxes, out);
}

// round 2
// speedup vs baseline: 2.2794x; 2.2794x over previous
#include <cuda_runtime.h>
#include <cuda_bf16.h>
#include <cstdint>

#define BB 2
#define QQ 300
#define TT 300
#define HH 256
#define WW 256
#define PP 12544
#define SPLITK 7
#define KC (PP / SPLITK)     // 1792
#define KITERS (KC / 64)     // 28
#define NTILES 5             // ceil(300/64)

#define NTY 8                // row tiles per mask
#define TROWS 32             // rows per tile
#define PPT 49               // points per thread in binning (256*49 = 12544)

// ---------------- scratch (device globals; no allocation allowed) ----------------
__device__ __nv_bfloat16 g_om[(size_t)BB * QQ * PP];
__device__ __nv_bfloat16 g_s [(size_t)BB * QQ * PP];
__device__ __nv_bfloat16 g_tm[(size_t)BB * TT * PP];
__device__ float g_negsum[BB * QQ];
__device__ float g_ssum [BB * QQ];
__device__ float g_tmsum [BB * TT];
__device__ float g_D1p[(size_t)SPLITK * BB * QQ * TT];
__device__ float g_D2p[(size_t)SPLITK * BB * QQ * TT];

// binning scratch
__device__ float2 g_spt[(size_t)BB * PP];          // pre-scaled coords, sorted by tile
__device__ unsigned short g_spi[(size_t)BB * PP];  // original point index
__device__ int g_binstart[BB][NTY + 1];
// per-(mask,tile) partial sums
__device__ float g_psA[BB * 600 * NTY];  // pred: sum softplus(om); tgt: sum tm
__device__ float g_psB[BB * 600 * NTY];  // pred: sum sigmoid(om)

// ---------------- kernel 0: deterministic counting sort of points by row-tile ----------------
__global__ __launch_bounds__(256) void bin_kernel(const float* __restrict__ point_coords)
{
    int b = blockIdx.x;
    int tid = threadIdx.x;
    const float2* pc = (const float2*)(point_coords + (size_t)b * PP * 2);

    __shared__ int hist[256 * NTY];
    __shared__ int total[NTY];
    __shared__ int binbase[NTY];

    int cnt[NTY];
    #pragma unroll
    for (int k = 0; k < NTY; k++) cnt[k] = 0;

    int start = tid * PPT;
    for (int j = 0; j < PPT; j++) {
        float2 pt = pc[start + j];
        float y = pt.y * (float)HH - 0.5f;
        int y0 = (int)floorf(y);
        int t = min(max(y0, 0), HH - 1) >> 5;
        cnt[t]++;
    }
    #pragma unroll
    for (int k = 0; k < NTY; k++) hist[tid * NTY + k] = cnt[k];
    __syncthreads();

    // per-bin exclusive prefix over threads (8 scanner threads)
    if (tid < NTY) {
        int run = 0;
        for (int t = 0; t < 256; t++) {
            int v = hist[t * NTY + tid];
            hist[t * NTY + tid] = run;
            run += v;
        }
        total[tid] = run;
    }
    __syncthreads();
    if (tid == 0) {
        int base = 0;
        for (int k = 0; k < NTY; k++) {
            binbase[k] = base;
            g_binstart[b][k] = base;
            base += total[k];
        }
        g_binstart[b][NTY] = base;  // == PP
    }
    __syncthreads();

    int off[NTY];
    #pragma unroll
    for (int k = 0; k < NTY; k++) off[k] = binbase[k] + hist[tid * NTY + k];

    for (int j = 0; j < PPT; j++) {
        int p = start + j;
        float2 pt = pc[p];
        float x = pt.x * (float)WW - 0.5f;
        float y = pt.y * (float)HH - 0.5f;
        int y0 = (int)floorf(y);
        int t = min(max(y0, 0), HH - 1) >> 5;
        int pos = off[t]++;
        g_spt[(size_t)b * PP + pos] = make_float2(x, y);
        g_spi[(size_t)b * PP + pos] = (unsigned short)p;
    }
}

// ---------------- kernel 1: tiled bilinear sampling (each mask element read once) ----------------
__global__ __launch_bounds__(256) void sample_kernel(
    const float* __restrict__ pred_masks,
    const float* __restrict__ tgt_masks)
{
    int bx = blockIdx.x;
    int tile = bx & (NTY - 1); bx >>= 3;
    int b = bx / 600;
    int r = bx % 600;
    bool is_pred = (r < 300);
    int m = is_pred ? r : r - 300;

    const float* mask = (is_pred ? pred_masks : tgt_masks) + ((size_t)(b * 300 + m)) * (HH * WW);
    size_t obase = (size_t)(b * 300 + m) * PP;

    __shared__ float sm[33 * WW];

    int row0 = tile * TROWS;
    int nrows = (tile == NTY - 1) ? TROWS : (TROWS + 1);

    // stage tile (+halo row) into smem, float4 loads
    int nvec = nrows * (WW / 4);
    for (int i = threadIdx.x; i < nvec; i += 256) {
        int row = i >> 6;
        int c = (i & 63) * 4;
        float4 v = __ldg((const float4*)(mask + (size_t)(row0 + row) * WW + c));
        *(float4*)&sm[row * WW + c] = v;
    }

    int pbeg = g_binstart[b][tile];
    int pend = g_binstart[b][tile + 1];
    __syncthreads();

    float s0 = 0.f, s1 = 0.f;
    const float2* spt = g_spt + (size_t)b * PP;
    const unsigned short* spi = g_spi + (size_t)b * PP;

    for (int j = pbeg + threadIdx.x; j < pend; j += 256) {
        float2 pt = spt[j];
        int p = spi[j];
        float x = pt.x, y = pt.y;
        float x0f = floorf(x), y0f = floorf(y);
        float wx = x - x0f, wy = y - y0f;
        int x0 = (int)x0f, y0 = (int)y0f;
        int x1 = x0 + 1, y1 = y0 + 1;
        int ly0 = y0 - row0, ly1 = ly0 + 1;

        bool vx0 = (x0 >= 0);           // x0 <= 255 always
        bool vx1 = (x1 <= WW - 1);      // x1 >= 0 always
        bool vy0 = (y0 >= 0);
        bool vy1 = (y1 <= HH - 1);

        float f00 = (vy0 && vx0) ? sm[ly0 * WW + x0] : 0.f;
        float f01 = (vy0 && vx1) ? sm[ly0 * WW + x1] : 0.f;
        float f10 = (vy1 && vx0) ? sm[ly1 * WW + x0] : 0.f;
        float f11 = (vy1 && vx1) ? sm[ly1 * WW + x1] : 0.f;

        float om = f00 * (1.f - wy) * (1.f - wx) + f01 * (1.f - wy) * wx +
                   f10 * wy * (1.f - wx) + f11 * wy * wx;

        if (is_pred) {
            float sg = 1.f / (1.f + __expf(-om));
            float neg = fmaxf(om, 0.f) + log1pf(__expf(-fabsf(om)));  // softplus(om)
            g_om[obase + p] = __float2bfloat16(om);
            g_s [obase + p] = __float2bfloat16(sg);
            s0 += neg;
            s1 += sg;
        } else {
            g_tm[obase + p] = __float2bfloat16(om);
            s0 += om;
        }
    }

    // block reduce
    #pragma unroll
    for (int o = 16; o > 0; o >>= 1) {
        s0 += __shfl_down_sync(0xffffffffu, s0, o);
        s1 += __shfl_down_sync(0xffffffffu, s1, o);
    }
    __shared__ float r0[8], r1[8];
    int lane = threadIdx.x & 31, warp = threadIdx.x >> 5;
    if (lane == 0) { r0[warp] = s0; r1[warp] = s1; }
    __syncthreads();
    if (threadIdx.x == 0) {
        float t0 = 0.f, t1 = 0.f;
        #pragma unroll
        for (int i = 0; i < 8; i++) { t0 += r0[i]; t1 += r1[i]; }
        int idx = (b * 600 + r) * NTY + tile;
        g_psA[idx] = t0;
        g_psB[idx] = t1;
    }
}

// ---------------- kernel 1b: reduce per-tile partials ----------------
__global__ void reduce_sums_kernel()
{
    int idx = blockIdx.x * 256 + threadIdx.x;
    if (idx >= BB * 600) return;
    int b = idx / 600, r = idx % 600;
    float a = 0.f, c = 0.f;
    #pragma unroll
    for (int k = 0; k < NTY; k++) {
        a += g_psA[idx * NTY + k];
        c += g_psB[idx * NTY + k];
    }
    if (r < 300) {
        g_negsum[b * 300 + r] = a;
        g_ssum [b * 300 + r] = c;
    } else {
        g_tmsum[b * 300 + (r - 300)] = a;
    }
}

// ---------------- mma helpers ----------------
__device__ __forceinline__ void ldsm_x4(uint32_t* r, const void* ptr) {
    uint32_t a = (uint32_t)__cvta_generic_to_shared(ptr);
    asm volatile("ldmatrix.sync.aligned.m8n8.x4.shared.b16 {%0,%1,%2,%3}, [%4];"
                 : "=r"(r[0]), "=r"(r[1]), "=r"(r[2]), "=r"(r[3]) : "r"(a));
}
__device__ __forceinline__ void ldsm_x2(uint32_t* r, const void* ptr) {
    uint32_t a = (uint32_t)__cvta_generic_to_shared(ptr);
    asm volatile("ldmatrix.sync.aligned.m8n8.x2.shared.b16 {%0,%1}, [%2];"
                 : "=r"(r[0]), "=r"(r[1]) : "r"(a));
}
__device__ __forceinline__ void mma16816(float* d, const uint32_t* a, const uint32_t* b) {
    asm volatile("mma.sync.aligned.m16n8k16.row.col.f32.bf16.bf16.f32 "
                 "{%0,%1,%2,%3}, {%4,%5,%6,%7}, {%8,%9}, {%0,%1,%2,%3};"
                 : "+f"(d[0]), "+f"(d[1]), "+f"(d[2]), "+f"(d[3])
                 : "r"(a[0]), "r"(a[1]), "r"(a[2]), "r"(a[3]), "r"(b[0]), "r"(b[1]));
}

// ---------------- kernel 2: dual bf16 GEMM (om*tm^T and s*tm^T), split-K ----------------
#define LDT 72  // 64 + 8 pad (bf16 elems)

__global__ __launch_bounds__(256) void gemm_kernel()
{
    int bx = blockIdx.x;
    int split = bx % SPLITK; bx /= SPLITK;
    int tt = bx % NTILES; bx /= NTILES;
    int qt = bx % NTILES;
    int b  = bx / NTILES;
    int m0 = qt * 64, n0 = tt * 64;

    __shared__ __nv_bfloat16 s_om[64 * LDT];
    __shared__ __nv_bfloat16 s_s [64 * LDT];
    __shared__ __nv_bfloat16 s_tm[64 * LDT];

    int tid = threadIdx.x;
    int warp = tid >> 5, lane = tid & 31;
    int wm0 = (warp >> 2) * 32;
    int wn0 = (warp & 3) * 16;

    float acc1[2][2][4];
    float acc2[2][2][4];
    #pragma unroll
    for (int i = 0; i < 2; i++)
        #pragma unroll
        for (int j = 0; j < 2; j++)
            #pragma unroll
            for (int k = 0; k < 4; k++) { acc1[i][j][k] = 0.f; acc2[i][j][k] = 0.f; }

    const __nv_bfloat16* Aom = g_om + (size_t)(b * 300) * PP;
    const __nv_bfloat16* As  = g_s  + (size_t)(b * 300) * PP;
    const __nv_bfloat16* Btm = g_tm + (size_t)(b * 300) * PP;

    int kbase = split * KC;
    for (int kt = 0; kt < KITERS; ++kt) {
        int k0 = kbase + kt * 64;
        #pragma unroll
        for (int i = tid; i < 512; i += 256) {
            int row = i >> 3;
            int c = (i & 7) * 8;
            int gq = m0 + row;
            int gt = n0 + row;
            uint4 z = make_uint4(0, 0, 0, 0);
            uint4 vo = z, vs = z, vt = z;
            if (gq < 300) {
                vo = __ldg((const uint4*)(Aom + (size_t)gq * PP + k0 + c));
                vs = __ldg((const uint4*)(As  + (size_t)gq * PP + k0 + c));
            }
            if (gt < 300) {
                vt = __ldg((const uint4*)(Btm + (size_t)gt * PP + k0 + c));
            }
            *(uint4*)&s_om[row * LDT + c] = vo;
            *(uint4*)&s_s [row * LDT + c] = vs;
            *(uint4*)&s_tm[row * LDT + c] = vt;
        }
        __syncthreads();

        #pragma unroll
        for (int ks = 0; ks < 4; ++ks) {
            uint32_t ao[2][4], av[2][4], bb[2][2];
            int arow = wm0 + (lane & 15);
            int acol = ks * 16 + (lane >> 4) * 8;
            #pragma unroll
            for (int ti = 0; ti < 2; ++ti) {
                ldsm_x4(ao[ti], &s_om[(arow + ti * 16) * LDT + acol]);
                ldsm_x4(av[ti], &s_s [(arow + ti * 16) * LDT + acol]);
            }
            int l16 = lane & 15;
            int brow = wn0 + (l16 & 7);
            int bcol = ks * 16 + (l16 >> 3) * 8;
            #pragma unroll
            for (int tn = 0; tn < 2; ++tn) {
                ldsm_x2(bb[tn], &s_tm[(brow + tn * 8) * LDT + bcol]);
            }
            #pragma unroll
            for (int ti = 0; ti < 2; ++ti)
                #pragma unroll
                for (int tn = 0; tn < 2; ++tn) {
                    mma16816(acc1[ti][tn], ao[ti], bb[tn]);
                    mma16816(acc2[ti][tn], av[ti], bb[tn]);
                }
        }
        __syncthreads();
    }

    float* D1 = g_D1p + ((size_t)(split * BB + b)) * (QQ * TT);
    float* D2 = g_D2p + ((size_t)(split * BB + b)) * (QQ * TT);
    #pragma unroll
    for (int ti = 0; ti < 2; ++ti)
        #pragma unroll
        for (int tn = 0; tn < 2; ++tn)
            #pragma unroll
            for (int rh = 0; rh < 2; ++rh) {
                int q = m0 + wm0 + ti * 16 + (lane >> 2) + rh * 8;
                int t = n0 + wn0 + tn * 8 + (lane & 3) * 2;
                if (q < QQ && t < TT) {
                    float2 v1 = make_float2(acc1[ti][tn][rh * 2 + 0], acc1[ti][tn][rh * 2 + 1]);
                    float2 v2 = make_float2(acc2[ti][tn][rh * 2 + 0], acc2[ti][tn][rh * 2 + 1]);
                    *(float2*)&D1[q * TT + t] = v1;
                    *(float2*)&D2[q * TT + t] = v2;
                }
            }
}

// ---------------- kernel 3: reduce partials + box costs + assemble ----------------
__global__ __launch_bounds__(256) void final_kernel(
    const float* __restrict__ pred_boxes,
    const float* __restrict__ tgt_boxes,
    float* __restrict__ out)
{
    int idx = blockIdx.x * 256 + threadIdx.x;
    if (idx >= BB * QQ * TT) return;
    int b = idx / (QQ * TT);
    int r = idx % (QQ * TT);
    int q = r / TT, t = r % TT;

    float D1 = 0.f, D2 = 0.f;
    #pragma unroll
    for (int s = 0; s < SPLITK; ++s) {
        size_t off = ((size_t)(s * BB + b)) * (QQ * TT) + r;
        D1 += g_D1p[off];
        D2 += g_D2p[off];
    }

    float ns = g_negsum[b * 300 + q];
    float ss = g_ssum [b * 300 + q];
    float ts = g_tmsum [b * 300 + t];

    float cost_mask = (ns - D1) * (1.f / (float)PP);
    float cost_dice = 1.f - (2.f * D2 + 1.f) / (ss + ts + 1.f);

    const float* pb = pred_boxes + (size_t)(b * 300 + q) * 4;
    const float* tb = tgt_boxes  + (size_t)(b * 300 + t) * 4;
    float p0 = pb[0], p1 = pb[1], p2 = pb[2], p3 = pb[3];
    float t0 = tb[0], t1 = tb[1], t2 = tb[2], t3 = tb[3];

    float cost_bbox = fabsf(p0 - t0) + fabsf(p1 - t1) + fabsf(p2 - t2) + fabsf(p3 - t3);

    float ax0 = p0 - 0.5f * p2, ay0 = p1 - 0.5f * p3;
    float ax1 = p0 + 0.5f * p2, ay1 = p1 + 0.5f * p3;
    float bx0 = t0 - 0.5f * t2, by0 = t1 - 0.5f * t3;
    float bx1 = t0 + 0.5f * t2, by1 = t1 + 0.5f * t3;

    float areaA = (ax1 - ax0) * (ay1 - ay0);
    float areaB = (bx1 - bx0) * (by1 - by0);
    float iw = fminf(ax1, bx1) - fmaxf(ax0, bx0);
    float ih = fminf(ay1, by1) - fmaxf(ay0, by0);
    iw = fmaxf(iw, 0.f); ih = fmaxf(ih, 0.f);
    float inter = iw * ih;
    float uni = areaA + areaB - inter;
    float iou = inter / uni;
    float ew = fmaxf(ax1, bx1) - fminf(ax0, bx0);
    float eh = fmaxf(ay1, by1) - fminf(ay0, by0);
    ew = fmaxf(ew, 0.f); eh = fmaxf(eh, 0.f);
    float ae = ew * eh;
    float giou = iou - (ae - uni) / ae;

    out[idx] = 5.f * cost_mask + 5.f * cost_dice + 5.f * cost_bbox - 2.f * giou;
}

// ---------------- launch ----------------
extern "C" void kernel_launch(void* const* d_in, const int* in_sizes, int n_in,
                              void* d_out, int out_size)
{
    const float* pred_masks   = (const float*)d_in[0];
    const float* tgt_masks    = (const float*)d_in[1];
    const float* pred_boxes   = (const float*)d_in[2];
    const float* tgt_boxes    = (const float*)d_in[3];
    const float* point_coords = (const float*)d_in[4];
    float* out = (float*)d_out;

    bin_kernel<<<BB, 256>>>(point_coords);
    sample_kernel<<<BB * 600 * NTY, 256>>>(pred_masks, tgt_masks);
    reduce_sums_kernel<<<(BB * 600 + 255) / 256, 256>>>();
    gemm_kernel<<<BB * NTILES * NTILES * SPLITK, 256>>>();
    final_kernel<<<(BB * QQ * TT + 255) / 256, 256>>>(pred_boxes, tgt_boxes, out);
}

// round 4
// speedup vs baseline: 2.9519x; 1.2951x over previous
#include <cuda_runtime.h>
#include <cuda_bf16.h>
#include <cstdint>

#define BB 2
#define QQ 300
#define TT 300
#define HH 256
#define WW 256
#define PP 12544
#define SPLITK 14
#define KC (PP / SPLITK)     // 896
#define KITERS (KC / 64)     // 14
#define NTILES 5             // ceil(300/64)

#define NTY 8                // row tiles per mask
#define TROWS 32
#define PPT 49               // 256*49 = 12544

// ---------------- scratch ----------------
__device__ __nv_bfloat16 g_om[(size_t)BB * QQ * PP];
__device__ __nv_bfloat16 g_s [(size_t)BB * QQ * PP];
__device__ __nv_bfloat16 g_tm[(size_t)BB * TT * PP];
__device__ float g_negsum[BB * QQ];
__device__ float g_ssum [BB * QQ];
__device__ float g_tmsum [BB * TT];
__device__ float g_D1p[(size_t)SPLITK * BB * QQ * TT];
__device__ float g_D2p[(size_t)SPLITK * BB * QQ * TT];

__device__ float2 g_spt[(size_t)BB * PP];          // pre-scaled coords, sorted by tile
__device__ int g_binstart[BB][NTY + 1];
__device__ float g_psA[BB * 600 * NTY];
__device__ float g_psB[BB * 600 * NTY];

// ---------------- kernel 0: deterministic counting sort of points by row-tile ----------------
__global__ __launch_bounds__(256) void bin_kernel(const float* __restrict__ point_coords)
{
    int b = blockIdx.x;
    int tid = threadIdx.x;
    const float2* pc = (const float2*)(point_coords + (size_t)b * PP * 2);

    __shared__ int hist[256 * NTY];
    __shared__ int total[NTY];
    __shared__ int binbase[NTY];

    int cnt[NTY];
    #pragma unroll
    for (int k = 0; k < NTY; k++) cnt[k] = 0;

    int start = tid * PPT;
    for (int j = 0; j < PPT; j++) {
        float2 pt = pc[start + j];
        float y = pt.y * (float)HH - 0.5f;
        int y0 = (int)floorf(y);
        int t = min(max(y0, 0), HH - 1) >> 5;
        cnt[t]++;
    }
    #pragma unroll
    for (int k = 0; k < NTY; k++) hist[tid * NTY + k] = cnt[k];
    __syncthreads();

    if (tid < NTY) {
        int run = 0;
        for (int t = 0; t < 256; t++) {
            int v = hist[t * NTY + tid];
            hist[t * NTY + tid] = run;
            run += v;
        }
        total[tid] = run;
    }
    __syncthreads();
    if (tid == 0) {
        int base = 0;
        for (int k = 0; k < NTY; k++) {
            binbase[k] = base;
            g_binstart[b][k] = base;
            base += total[k];
        }
        g_binstart[b][NTY] = base;
    }
    __syncthreads();

    int off[NTY];
    #pragma unroll
    for (int k = 0; k < NTY; k++) off[k] = binbase[k] + hist[tid * NTY + k];

    for (int j = 0; j < PPT; j++) {
        float2 pt = pc[start + j];
        float x = pt.x * (float)WW - 0.5f;
        float y = pt.y * (float)HH - 0.5f;
        int y0 = (int)floorf(y);
        int t = min(max(y0, 0), HH - 1) >> 5;
        int pos = off[t]++;
        g_spt[(size_t)b * PP + pos] = make_float2(x, y);
    }
}

// ---------------- kernel 1: tiled sampling, COALESCED stores in sorted order ----------------
__global__ __launch_bounds__(256) void sample_kernel(
    const float* __restrict__ pred_masks,
    const float* __restrict__ tgt_masks)
{
    int bx = blockIdx.x;
    int tile = bx & (NTY - 1); bx >>= 3;
    int b = bx / 600;
    int r = bx % 600;
    bool is_pred = (r < 300);
    int m = is_pred ? r : r - 300;

    const float* mask = (is_pred ? pred_masks : tgt_masks) + ((size_t)(b * 300 + m)) * (HH * WW);
    size_t obase = (size_t)(b * 300 + m) * PP;

    __shared__ float sm[33 * WW];

    int row0 = tile * TROWS;
    int nrows = (tile == NTY - 1) ? TROWS : (TROWS + 1);

    int nvec = nrows * (WW / 4);
    for (int i = threadIdx.x; i < nvec; i += 256) {
        int row = i >> 6;
        int c = (i & 63) * 4;
        float4 v = __ldg((const float4*)(mask + (size_t)(row0 + row) * WW + c));
        *(float4*)&sm[row * WW + c] = v;
    }

    int pbeg = g_binstart[b][tile];
    int pend = g_binstart[b][tile + 1];
    __syncthreads();

    float s0 = 0.f, s1 = 0.f;
    const float2* spt = g_spt + (size_t)b * PP;

    for (int j = pbeg + threadIdx.x; j < pend; j += 256) {
        float2 pt = spt[j];
        float x = pt.x, y = pt.y;
        float x0f = floorf(x), y0f = floorf(y);
        float wx = x - x0f, wy = y - y0f;
        int x0 = (int)x0f, y0 = (int)y0f;
        int x1 = x0 + 1, y1 = y0 + 1;
        int ly0 = y0 - row0, ly1 = ly0 + 1;

        bool vx0 = (x0 >= 0);
        bool vx1 = (x1 <= WW - 1);
        bool vy0 = (y0 >= 0);
        bool vy1 = (y1 <= HH - 1);

        float f00 = (vy0 && vx0) ? sm[ly0 * WW + x0] : 0.f;
        float f01 = (vy0 && vx1) ? sm[ly0 * WW + x1] : 0.f;
        float f10 = (vy1 && vx0) ? sm[ly1 * WW + x0] : 0.f;
        float f11 = (vy1 && vx1) ? sm[ly1 * WW + x1] : 0.f;

        float om = f00 * (1.f - wy) * (1.f - wx) + f01 * (1.f - wy) * wx +
                   f10 * wy * (1.f - wx) + f11 * wy * wx;

        // store at SORTED index j -> fully coalesced (same permutation for om/s/tm)
        if (is_pred) {
            float sg = 1.f / (1.f + __expf(-om));
            float neg = fmaxf(om, 0.f) + log1pf(__expf(-fabsf(om)));
            g_om[obase + j] = __float2bfloat16(om);
            g_s [obase + j] = __float2bfloat16(sg);
            s0 += neg;
            s1 += sg;
        } else {
            g_tm[obase + j] = __float2bfloat16(om);
            s0 += om;
        }
    }

    #pragma unroll
    for (int o = 16; o > 0; o >>= 1) {
        s0 += __shfl_down_sync(0xffffffffu, s0, o);
        s1 += __shfl_down_sync(0xffffffffu, s1, o);
    }
    __shared__ float r0[8], r1[8];
    int lane = threadIdx.x & 31, warp = threadIdx.x >> 5;
    if (lane == 0) { r0[warp] = s0; r1[warp] = s1; }
    __syncthreads();
    if (threadIdx.x == 0) {
        float t0 = 0.f, t1 = 0.f;
        #pragma unroll
        for (int i = 0; i < 8; i++) { t0 += r0[i]; t1 += r1[i]; }
        int idx = (b * 600 + r) * NTY + tile;
        g_psA[idx] = t0;
        g_psB[idx] = t1;
    }
}

// ---------------- kernel 1b ----------------
__global__ void reduce_sums_kernel()
{
    int idx = blockIdx.x * 256 + threadIdx.x;
    if (idx >= BB * 600) return;
    int b = idx / 600, r = idx % 600;
    float a = 0.f, c = 0.f;
    #pragma unroll
    for (int k = 0; k < NTY; k++) {
        a += g_psA[idx * NTY + k];
        c += g_psB[idx * NTY + k];
    }
    if (r < 300) {
        g_negsum[b * 300 + r] = a;
        g_ssum [b * 300 + r] = c;
    } else {
        g_tmsum[b * 300 + (r - 300)] = a;
    }
}

// ---------------- mma helpers ----------------
__device__ __forceinline__ void ldsm_x4_a(uint32_t* r, uint32_t a) {
    asm volatile("ldmatrix.sync.aligned.m8n8.x4.shared.b16 {%0,%1,%2,%3}, [%4];"
                 : "=r"(r[0]), "=r"(r[1]), "=r"(r[2]), "=r"(r[3]) : "r"(a));
}
__device__ __forceinline__ void ldsm_x2_a(uint32_t* r, uint32_t a) {
    asm volatile("ldmatrix.sync.aligned.m8n8.x2.shared.b16 {%0,%1}, [%2];"
                 : "=r"(r[0]), "=r"(r[1]) : "r"(a));
}
__device__ __forceinline__ void mma16816(float* d, const uint32_t* a, const uint32_t* b) {
    asm volatile("mma.sync.aligned.m16n8k16.row.col.f32.bf16.bf16.f32 "
                 "{%0,%1,%2,%3}, {%4,%5,%6,%7}, {%8,%9}, {%0,%1,%2,%3};"
                 : "+f"(d[0]), "+f"(d[1]), "+f"(d[2]), "+f"(d[3])
                 : "r"(a[0]), "r"(a[1]), "r"(a[2]), "r"(a[3]), "r"(b[0]), "r"(b[1]));
}
__device__ __forceinline__ void cp16(uint32_t dst, const void* src, bool pred) {
    int sz = pred ? 16 : 0;
    asm volatile("cp.async.cg.shared.global [%0], [%1], 16, %2;"
                 :: "r"(dst), "l"(src), "r"(sz));
}

// swizzled byte offset within a 64x64 bf16 tile (8KB): row-major 128B rows,
// 16B chunk c XOR (row&7) -> conflict-free ldmatrix + cp.async
__device__ __forceinline__ uint32_t sw_off(int row, int col_e) {
    int chunk = col_e >> 3;
    return (uint32_t)(row * 128 + ((chunk ^ (row & 7)) << 4));
}

// ---------------- kernel 2: dual bf16 GEMM, 2-stage cp.async pipeline ----------------
__global__ __launch_bounds__(256) void gemm_kernel()
{
    int bx = blockIdx.x;
    int split = bx % SPLITK; bx /= SPLITK;
    int tt = bx % NTILES; bx /= NTILES;
    int qt = bx % NTILES;
    int b  = bx / NTILES;
    int m0 = qt * 64, n0 = tt * 64;

    // [stage][array: 0=om,1=s,2=tm][8KB]
    __shared__ __align__(16) unsigned char smem[2][3][8192];
    uint32_t smem_base = (uint32_t)__cvta_generic_to_shared(&smem[0][0][0]);

    int tid = threadIdx.x;
    int warp = tid >> 5, lane = tid & 31;
    int wm0 = (warp >> 2) * 32;
    int wn0 = (warp & 3) * 16;

    float acc1[2][2][4];
    float acc2[2][2][4];
    #pragma unroll
    for (int i = 0; i < 2; i++)
        #pragma unroll
        for (int j = 0; j < 2; j++)
            #pragma unroll
            for (int k = 0; k < 4; k++) { acc1[i][j][k] = 0.f; acc2[i][j][k] = 0.f; }

    const __nv_bfloat16* Aom = g_om + (size_t)(b * 300) * PP;
    const __nv_bfloat16* As  = g_s  + (size_t)(b * 300) * PP;
    const __nv_bfloat16* Btm = g_tm + (size_t)(b * 300) * PP;

    int kbase = split * KC;

    // per-thread chunk assignment: 1536 16B chunks, 6 per thread
    // i = a*512 + row*8 + ch
    auto load_stage = [&](int kt, int st) {
        int k0 = kbase + kt * 64;
        #pragma unroll
        for (int u = 0; u < 6; ++u) {
            int i = tid + u * 256;
            int a = i >> 9;
            int rem = i & 511;
            int row = rem >> 3;
            int ch = rem & 7;
            uint32_t dst = smem_base + (uint32_t)((st * 3 + a) * 8192) + sw_off(row, ch * 8);
            const __nv_bfloat16* srcbase = (a == 0) ? Aom : (a == 1) ? As : Btm;
            int g = ((a == 2) ? n0 : m0) + row;
            bool pred = (g < 300);
            const void* src = srcbase + (size_t)min(g, 299) * PP + k0 + ch * 8;
            cp16(dst, src, pred);
        }
        asm volatile("cp.async.commit_group;" ::: "memory");
    };

    load_stage(0, 0);

    for (int kt = 0; kt < KITERS; ++kt) {
        int st = kt & 1;
        if (kt + 1 < KITERS) {
            load_stage(kt + 1, (kt + 1) & 1);
            asm volatile("cp.async.wait_group 1;" ::: "memory");
        } else {
            asm volatile("cp.async.wait_group 0;" ::: "memory");
        }
        __syncthreads();

        uint32_t base_om = smem_base + (uint32_t)((st * 3 + 0) * 8192);
        uint32_t base_s  = smem_base + (uint32_t)((st * 3 + 1) * 8192);
        uint32_t base_tm = smem_base + (uint32_t)((st * 3 + 2) * 8192);

        #pragma unroll
        for (int ks = 0; ks < 4; ++ks) {
            uint32_t ao[2][4], av[2][4], bb[2][2];
            int arow = wm0 + (lane & 15);
            int acol = ks * 16 + (lane >> 4) * 8;
            #pragma unroll
            for (int ti = 0; ti < 2; ++ti) {
                ldsm_x4_a(ao[ti], base_om + sw_off(arow + ti * 16, acol));
                ldsm_x4_a(av[ti], base_s  + sw_off(arow + ti * 16, acol));
            }
            int l16 = lane & 15;
            int brow = wn0 + (l16 & 7);
            int bcol = ks * 16 + (l16 >> 3) * 8;
            #pragma unroll
            for (int tn = 0; tn < 2; ++tn) {
                ldsm_x2_a(bb[tn], base_tm + sw_off(brow + tn * 8, bcol));
            }
            #pragma unroll
            for (int ti = 0; ti < 2; ++ti)
                #pragma unroll
                for (int tn = 0; tn < 2; ++tn) {
                    mma16816(acc1[ti][tn], ao[ti], bb[tn]);
                    mma16816(acc2[ti][tn], av[ti], bb[tn]);
                }
        }
        __syncthreads();
    }

    float* D1 = g_D1p + ((size_t)(split * BB + b)) * (QQ * TT);
    float* D2 = g_D2p + ((size_t)(split * BB + b)) * (QQ * TT);
    #pragma unroll
    for (int ti = 0; ti < 2; ++ti)
        #pragma unroll
        for (int tn = 0; tn < 2; ++tn)
            #pragma unroll
            for (int rh = 0; rh < 2; ++rh) {
                int q = m0 + wm0 + ti * 16 + (lane >> 2) + rh * 8;
                int t = n0 + wn0 + tn * 8 + (lane & 3) * 2;
                if (q < QQ && t < TT) {
                    float2 v1 = make_float2(acc1[ti][tn][rh * 2 + 0], acc1[ti][tn][rh * 2 + 1]);
                    float2 v2 = make_float2(acc2[ti][tn][rh * 2 + 0], acc2[ti][tn][rh * 2 + 1]);
                    *(float2*)&D1[q * TT + t] = v1;
                    *(float2*)&D2[q * TT + t] = v2;
                }
            }
}

// ---------------- kernel 3 ----------------
__global__ __launch_bounds__(256) void final_kernel(
    const float* __restrict__ pred_boxes,
    const float* __restrict__ tgt_boxes,
    float* __restrict__ out)
{
    int idx = blockIdx.x * 256 + threadIdx.x;
    if (idx >= BB * QQ * TT) return;
    int b = idx / (QQ * TT);
    int r = idx % (QQ * TT);
    int q = r / TT, t = r % TT;

    float D1 = 0.f, D2 = 0.f;
    #pragma unroll
    for (int s = 0; s < SPLITK; ++s) {
        size_t off = ((size_t)(s * BB + b)) * (QQ * TT) + r;
        D1 += g_D1p[off];
        D2 += g_D2p[off];
    }

    float ns = g_negsum[b * 300 + q];
    float ss = g_ssum [b * 300 + q];
    float ts = g_tmsum [b * 300 + t];

    float cost_mask = (ns - D1) * (1.f / (float)PP);
    float cost_dice = 1.f - (2.f * D2 + 1.f) / (ss + ts + 1.f);

    const float* pb = pred_boxes + (size_t)(b * 300 + q) * 4;
    const float* tb = tgt_boxes  + (size_t)(b * 300 + t) * 4;
    float p0 = pb[0], p1 = pb[1], p2 = pb[2], p3 = pb[3];
    float t0 = tb[0], t1 = tb[1], t2 = tb[2], t3 = tb[3];

    float cost_bbox = fabsf(p0 - t0) + fabsf(p1 - t1) + fabsf(p2 - t2) + fabsf(p3 - t3);

    float ax0 = p0 - 0.5f * p2, ay0 = p1 - 0.5f * p3;
    float ax1 = p0 + 0.5f * p2, ay1 = p1 + 0.5f * p3;
    float bx0 = t0 - 0.5f * t2, by0 = t1 - 0.5f * t3;
    float bx1 = t0 + 0.5f * t2, by1 = t1 + 0.5f * t3;

    float areaA = (ax1 - ax0) * (ay1 - ay0);
    float areaB = (bx1 - bx0) * (by1 - by0);
    float iw = fminf(ax1, bx1) - fmaxf(ax0, bx0);
    float ih = fminf(ay1, by1) - fmaxf(ay0, by0);
    iw = fmaxf(iw, 0.f); ih = fmaxf(ih, 0.f);
    float inter = iw * ih;
    float uni = areaA + areaB - inter;
    float iou = inter / uni;
    float ew = fmaxf(ax1, bx1) - fminf(ax0, bx0);
    float eh = fmaxf(ay1, by1) - fminf(ay0, by0);
    ew = fmaxf(ew, 0.f); eh = fmaxf(eh, 0.f);
    float ae = ew * eh;
    float giou = iou - (ae - uni) / ae;

    out[idx] = 5.f * cost_mask + 5.f * cost_dice + 5.f * cost_bbox - 2.f * giou;
}

// ---------------- launch ----------------
extern "C" void kernel_launch(void* const* d_in, const int* in_sizes, int n_in,
                              void* d_out, int out_size)
{
    const float* pred_masks   = (const float*)d_in[0];
    const float* tgt_masks    = (const float*)d_in[1];
    const float* pred_boxes   = (const float*)d_in[2];
    const float* tgt_boxes    = (const float*)d_in[3];
    const float* point_coords = (const float*)d_in[4];
    float* out = (float*)d_out;

    bin_kernel<<<BB, 256>>>(point_coords);
    sample_kernel<<<BB * 600 * NTY, 256>>>(pred_masks, tgt_masks);
    reduce_sums_kernel<<<(BB * 600 + 255) / 256, 256>>>();
    gemm_kernel<<<BB * NTILES * NTILES * SPLITK, 256>>>();
    final_kernel<<<(BB * QQ * TT + 255) / 256, 256>>>(pred_boxes, tgt_boxes, out);
}